// round 15
// baseline (speedup 1.0000x reference)
#include <cuda_runtime.h>
#include <math.h>

#define BB 64
#define NN 512
#define EE 128
#define FEATN 33
#define ROWS (BB*NN)
#define LARGEF 1000000.0f
#define NCHUNK 4
#define BCHUNK (BB / NCHUNK)   // 16 batches per chunk

__device__ float g_feat[(size_t)ROWS * FEATN];

// ---------------------------------------------------------------------------
// warp reduction helpers
// ---------------------------------------------------------------------------
__device__ __forceinline__ float wsum(float v) {
#pragma unroll
    for (int o = 16; o > 0; o >>= 1) v += __shfl_xor_sync(0xFFFFFFFFu, v, o);
    return v;
}
__device__ __forceinline__ unsigned uredsum(unsigned v) {
    return __reduce_add_sync(0xFFFFFFFFu, v);
}
__device__ __forceinline__ float fredmin_pos(float v) {
    return __int_as_float(__reduce_min_sync(0xFFFFFFFFu, __float_as_int(v)));
}

// ---------------------------------------------------------------------------
// Feature kernel (R14-measured form) + batch-chunk offset + late PDL trigger.
// ---------------------------------------------------------------------------
__global__ __launch_bounds__(256, 5) void feat_kernel(const float* __restrict__ pos,
                                                      const void* __restrict__ mask,
                                                      int b0) {
    __shared__ float2 sp[NN];
    __shared__ float2 spRow[8];
    const int b   = b0 + blockIdx.y;
    const int bx  = blockIdx.x;
    const int tid = threadIdx.x;

    // ---- inline mask dtype detection (first 256 uint4 = 4KB) ----
    int flags;
    {
        const uint4 v = ((const uint4*)mask)[tid];
        int u = 0, f = 0;
        unsigned w;
        w = v.x; if (w == 0x3F800000u) f = 1; else if (w > 1u) u = 1;
        w = v.y; if (w == 0x3F800000u) f = 1; else if (w > 1u) u = 1;
        w = v.z; if (w == 0x3F800000u) f = 1; else if (w > 1u) u = 1;
        w = v.w; if (w == 0x3F800000u) f = 1; else if (w > 1u) u = 1;
        flags = __syncthreads_or(u | (f << 1));
    }
    const int mode = (flags & 1) ? 1 : ((flags & 2) ? 2 : 0);

    // ---- stage positions (penalty embedded in x): two per thread ----
#pragma unroll
    for (int h = 0; h < 2; h++) {
        const int idx = tid + h * 256;
        const int gi = b * NN + idx;
        const float2 pxy = ((const float2*)pos)[gi];
        bool m;
        if (mode == 1)      m = ((const unsigned char*)mask)[gi] != 0;
        else if (mode == 2) m = ((const float*)mask)[gi] != 0.0f;
        else                m = ((const int*)mask)[gi] != 0;
        sp[idx] = make_float2(pxy.x + (m ? LARGEF : 0.0f), pxy.y);
        const int rloc = idx - bx * 8;
        if ((unsigned)rloc < 8u) spRow[rloc] = pxy;
    }
    __syncthreads();

    const int warp = tid >> 5, lane = tid & 31;
    const int i = bx * 8 + warp;
    const float2 pi = spRow[warp];
    const float xi = pi.x, yi = pi.y;
    const int  i_hi  = i >> 5;
    const bool pself = (lane == (i & 31));
    const float2* spl = sp + lane;

    unsigned cntUp = 0u, cntDn = 0u, cntLat = 0u;
    unsigned scntLo = 0u, scntHi = 0u;
    float mdUp2 = LARGEF, mdDn2 = LARGEF, mdLat2 = LARGEF;
    float smin2[8];
#pragma unroll
    for (int k = 0; k < 8; k++) smin2[k] = LARGEF;
    float sumd = 0.0f;

#pragma unroll
    for (int j0 = 0; j0 < 16; j0++) {
        const float2 p = spl[j0 << 5];
        const float dx = p.x - xi;
        const float dy = p.y - yi;
        const float d2 = __fadd_rn(__fadd_rn(__fmul_rn(dx, dx), __fmul_rn(dy, dy)), 1e-8f);
        float q2 = d2;
        if ((j0 == i_hi) && pself) q2 = LARGEF;
        const bool valid = q2 < 100000.0f;

        const float hay = 0.5f * fabsf(dy);
        const bool up = dx >  hay;
        const bool dn = dx < -hay;
        const bool lat = !up && !dn;

        const unsigned pat = (q2 < 9.0f)   ? 0x01010101u
                           : (q2 < 25.0f)  ? 0x01010100u
                           : (q2 < 64.0f)  ? 0x01010000u
                           : (q2 < 144.0f) ? 0x01000000u : 0u;
        if (up)  cntUp  += pat;
        if (dn)  cntDn  += pat;
        if (lat) cntLat += pat;

        if (up)  mdUp2  = fminf(mdUp2,  q2);
        if (dn)  mdDn2  = fminf(mdDn2,  q2);
        if (lat) mdLat2 = fminf(mdLat2, q2);

        const float su = dx + dy, sv = dy - dx;
        const int s = (dy < 0.0f)
            ? ((dx < 0.0f) ? ((sv > 0.0f) ? 0 : 1) : ((su < 0.0f) ? 2 : 3))
            : ((dx > 0.0f) ? ((sv < 0.0f) ? 4 : 5) : ((su > 0.0f) ? 6 : 7));

        const unsigned sinc = 1u << ((s & 3) << 3);
        if (valid) { if (s < 4) scntLo += sinc; else scntHi += sinc; }
#pragma unroll
        for (int k = 0; k < 8; k++)
            if (s == k) smin2[k] = fminf(smin2[k], q2);

        const float dist = d2 * rsqrtf(d2);
        if (valid) sumd += dist;
    }

    unsigned cntu[12];
#pragma unroll
    for (int t = 0; t < 4; t++) {
        cntu[0 * 4 + t] = uredsum((cntUp  >> (t * 8)) & 255u);
        cntu[1 * 4 + t] = uredsum((cntDn  >> (t * 8)) & 255u);
        cntu[2 * 4 + t] = uredsum((cntLat >> (t * 8)) & 255u);
    }
    unsigned scu[8];
#pragma unroll
    for (int k = 0; k < 8; k++)
        scu[k] = uredsum((k < 4 ? (scntLo >> (k * 8)) : (scntHi >> ((k - 4) * 8))) & 255u);
#pragma unroll
    for (int k = 0; k < 8; k++) smin2[k] = fredmin_pos(smin2[k]);
    mdUp2 = fredmin_pos(mdUp2); mdDn2 = fredmin_pos(mdDn2); mdLat2 = fredmin_pos(mdLat2);
    sumd = wsum(sumd);

    if (lane == 0) {
        float* o = g_feat + (size_t)(b * NN + i) * FEATN;
#pragma unroll
        for (int t = 0; t < 4; t++) {
            o[t * 3 + 0] = (float)cntu[0 * 4 + t];
            o[t * 3 + 1] = (float)cntu[1 * 4 + t];
            o[t * 3 + 2] = (float)cntu[2 * 4 + t];
        }
        o[12] = fminf(sqrtf(mdUp2)  / 10.0f, 1.0f);
        o[13] = fminf(sqrtf(mdDn2)  / 10.0f, 1.0f);
        o[14] = fminf(sqrtf(mdLat2) / 10.0f, 1.0f);
        unsigned cntv = 0;
#pragma unroll
        for (int k = 0; k < 8; k++) {
            o[15 + 2 * k] = (float)scu[k];
            o[16 + 2 * k] = fminf(sqrtf(smin2[k]) / 10.0f, 1.0f);
            cntv += scu[k];
        }
        o[31] = (float)(cntu[3] + cntu[7] + cntu[11]);
        float vc = fmaxf((float)cntv, 1.0f);
        o[32] = fminf(sumd / vc / 10.0f, 1.0f);
    }

    // Late PDL trigger: release the dependent enc_k launch only once this
    // block's work is done (visibility is enforced by enc's griddepsync).
    cudaTriggerProgrammaticLaunchCompletion();
}

// ---------------------------------------------------------------------------
// Encoder (R14-frozen shape) + row-block offset + PDL prologue:
// griddepsync (wait for feat chunk), then trigger (release next feat chunk).
// ---------------------------------------------------------------------------
#define XP 36
#define HP 132

__global__ __launch_bounds__(128, 8) void encoder_kernel(
    const float* __restrict__ W1, const float* __restrict__ b1,
    const float* __restrict__ gamma, const float* __restrict__ beta,
    const float* __restrict__ W2, const float* __restrict__ b2,
    float* __restrict__ out, int blk0)
{
    __shared__ float sx[16 * XP];
    __shared__ float sh[16 * HP];
    __shared__ float sred[16 * 4];

    // Wait for our feat chunk's writes, then let the NEXT feat chunk launch
    // and run fully concurrent with this encoder chunk.
    cudaGridDependencySynchronize();
    cudaTriggerProgrammaticLaunchCompletion();

    const int tid   = threadIdx.x;
    const int cg    = tid & 63;
    const int rg    = tid >> 6;
    const int lane  = tid & 31;
    const int whalf = cg >> 5;
    const int c0    = cg * 2;
    const int r0    = rg * 8;
    const int rowBase = (blk0 + blockIdx.x) * 16;

    for (int idx = tid; idx < 16 * FEATN; idx += 128) {
        int r = idx / FEATN, f = idx - r * FEATN;
        sx[r * XP + f] = g_feat[(size_t)rowBase * FEATN + idx];
    }
    if (tid < 48) {
        int r = tid / 3;
        sx[r * XP + FEATN + tid % 3] = 0.0f;
    }
    __syncthreads();

    float accA[8], accB[8];
    {
        const float2 bb = __ldg((const float2*)&b1[c0]);
#pragma unroll
        for (int rr = 0; rr < 8; rr++) { accA[rr] = bb.x; accB[rr] = bb.y; }
#pragma unroll 2
        for (int f4 = 0; f4 < 32; f4 += 4) {
            const float2 w0 = __ldg((const float2*)&W1[(f4 + 0) * EE + c0]);
            const float2 w1 = __ldg((const float2*)&W1[(f4 + 1) * EE + c0]);
            const float2 w2 = __ldg((const float2*)&W1[(f4 + 2) * EE + c0]);
            const float2 w3 = __ldg((const float2*)&W1[(f4 + 3) * EE + c0]);
#pragma unroll
            for (int rr = 0; rr < 8; rr++) {
                const float4 xv = *(const float4*)&sx[(r0 + rr) * XP + f4];
                accA[rr] += xv.x * w0.x + xv.y * w1.x + xv.z * w2.x + xv.w * w3.x;
                accB[rr] += xv.x * w0.y + xv.y * w1.y + xv.z * w2.y + xv.w * w3.y;
            }
        }
        const float2 wl = __ldg((const float2*)&W1[32 * EE + c0]);
#pragma unroll
        for (int rr = 0; rr < 8; rr++) {
            const float xl = sx[(r0 + rr) * XP + 32];
            accA[rr] += xl * wl.x;
            accB[rr] += xl * wl.y;
        }
    }

#pragma unroll
    for (int rr = 0; rr < 8; rr++) {
        float s  = wsum(accA[rr] + accB[rr]);
        float sq = wsum(accA[rr] * accA[rr] + accB[rr] * accB[rr]);
        if (lane == 0) {
            const int r = r0 + rr;
            sred[r * 4 + whalf * 2 + 0] = s;
            sred[r * 4 + whalf * 2 + 1] = sq;
        }
    }
    __syncthreads();

    const float2 gv  = __ldg((const float2*)&gamma[c0]);
    const float2 bev = __ldg((const float2*)&beta[c0]);
#pragma unroll
    for (int rr = 0; rr < 8; rr++) {
        const int r = r0 + rr;
        const float s  = sred[r * 4 + 0] + sred[r * 4 + 2];
        const float sq = sred[r * 4 + 1] + sred[r * 4 + 3];
        const float mu  = s * (1.0f / 128.0f);
        const float var = sq * (1.0f / 128.0f) - mu * mu;
        const float inv = 1.0f / sqrtf(var + 1e-5f);
        float hA = (accA[rr] - mu) * inv * gv.x + bev.x;
        float hB = (accB[rr] - mu) * inv * gv.y + bev.y;
        hA = 0.5f * hA * (1.0f + erff(hA * 0.70710678118654752440f));
        hB = 0.5f * hB * (1.0f + erff(hB * 0.70710678118654752440f));
        *(float2*)&sh[r * HP + c0] = make_float2(hA, hB);
    }
    __syncthreads();

    float oA[8], oB[8];
    {
        const float2 bo = __ldg((const float2*)&b2[c0]);
#pragma unroll
        for (int rr = 0; rr < 8; rr++) { oA[rr] = bo.x; oB[rr] = bo.y; }
#pragma unroll 4
        for (int k4 = 0; k4 < EE; k4 += 4) {
            const float2 w0 = __ldg((const float2*)&W2[(k4 + 0) * EE + c0]);
            const float2 w1 = __ldg((const float2*)&W2[(k4 + 1) * EE + c0]);
            const float2 w2 = __ldg((const float2*)&W2[(k4 + 2) * EE + c0]);
            const float2 w3 = __ldg((const float2*)&W2[(k4 + 3) * EE + c0]);
#pragma unroll
            for (int rr = 0; rr < 8; rr++) {
                const float4 hv = *(const float4*)&sh[(r0 + rr) * HP + k4];
                oA[rr] += hv.x * w0.x + hv.y * w1.x + hv.z * w2.x + hv.w * w3.x;
                oB[rr] += hv.x * w0.y + hv.y * w1.y + hv.z * w2.y + hv.w * w3.y;
            }
        }
    }
#pragma unroll
    for (int rr = 0; rr < 8; rr++) {
        float2 o2 = make_float2(oA[rr], oB[rr]);
        *(float2*)&out[(size_t)(rowBase + r0 + rr) * EE + c0] = o2;
    }
}

// ---------------------------------------------------------------------------
// Launch: 4-chunk software pipeline via PDL. Stream order:
//   feat0, enc0(PDL), feat1(PDL), enc1(PDL), ...
// enc_k griddepsyncs on feat_k then triggers -> feat_{k+1} overlaps enc_k.
// ---------------------------------------------------------------------------
extern "C" void kernel_launch(void* const* d_in, const int* in_sizes, int n_in,
                              void* d_out, int out_size) {
    const float* positions = (const float*)d_in[0];
    const void*  mask      = d_in[1];
    const float* W1        = (const float*)d_in[2];
    const float* b1        = (const float*)d_in[3];
    const float* gamma     = (const float*)d_in[4];
    const float* beta      = (const float*)d_in[5];
    const float* W2        = (const float*)d_in[6];
    const float* b2        = (const float*)d_in[7];
    float* out = (float*)d_out;

    cudaLaunchAttribute pdl;
    pdl.id = cudaLaunchAttributeProgrammaticStreamSerialization;
    pdl.val.programmaticStreamSerializationAllowed = 1;

    const int encBlocksPerChunk = (BCHUNK * NN) / 16;   // 512

    for (int k = 0; k < NCHUNK; k++) {
        // feat chunk k
        {
            cudaLaunchConfig_t cfg = {};
            cfg.gridDim  = dim3(NN / 8, BCHUNK, 1);
            cfg.blockDim = dim3(256, 1, 1);
            cfg.dynamicSmemBytes = 0;
            cfg.stream = 0;
            if (k > 0) { cfg.attrs = &pdl; cfg.numAttrs = 1; }
            cudaLaunchKernelEx(&cfg, feat_kernel, positions, mask, k * BCHUNK);
        }
        // encoder chunk k
        {
            cudaLaunchConfig_t cfg = {};
            cfg.gridDim  = dim3(encBlocksPerChunk, 1, 1);
            cfg.blockDim = dim3(128, 1, 1);
            cfg.dynamicSmemBytes = 0;
            cfg.stream = 0;
            cfg.attrs = &pdl; cfg.numAttrs = 1;
            cudaLaunchKernelEx(&cfg, encoder_kernel, W1, b1, gamma, beta,
                               W2, b2, out, k * encBlocksPerChunk);
        }
    }
}

// round 16
// speedup vs baseline: 1.1025x; 1.1025x over previous
#include <cuda_runtime.h>
#include <math.h>

#define BB 64
#define NN 512
#define EE 128
#define FEATN 33
#define ROWS (BB*NN)
#define LARGEF 1000000.0f

__device__ float g_feat[(size_t)ROWS * FEATN];

// ---------------------------------------------------------------------------
// warp reduction helpers
// ---------------------------------------------------------------------------
__device__ __forceinline__ float wsum(float v) {
#pragma unroll
    for (int o = 16; o > 0; o >>= 1) v += __shfl_xor_sync(0xFFFFFFFFu, v, o);
    return v;
}
__device__ __forceinline__ unsigned uredsum(unsigned v) {
    return __reduce_add_sync(0xFFFFFFFFu, v);
}
__device__ __forceinline__ float fredmin_pos(float v) {
    return __int_as_float(__reduce_min_sync(0xFFFFFFFFu, __float_as_int(v)));
}

// ---------------------------------------------------------------------------
// Feature kernel (exact R14 form, measured ~66us): 256 threads, 8 rows/block,
// 5 CTAs/SM. Pad penalty embedded in x; squared-distance domain.
// ---------------------------------------------------------------------------
__global__ __launch_bounds__(256, 5) void feat_kernel(const float* __restrict__ pos,
                                                      const void* __restrict__ mask) {
    __shared__ float2 sp[NN];
    __shared__ float2 spRow[8];
    const int b   = blockIdx.y;
    const int bx  = blockIdx.x;
    const int tid = threadIdx.x;

    // ---- inline mask dtype detection (first 256 uint4 = 4KB) ----
    int flags;
    {
        const uint4 v = ((const uint4*)mask)[tid];
        int u = 0, f = 0;
        unsigned w;
        w = v.x; if (w == 0x3F800000u) f = 1; else if (w > 1u) u = 1;
        w = v.y; if (w == 0x3F800000u) f = 1; else if (w > 1u) u = 1;
        w = v.z; if (w == 0x3F800000u) f = 1; else if (w > 1u) u = 1;
        w = v.w; if (w == 0x3F800000u) f = 1; else if (w > 1u) u = 1;
        flags = __syncthreads_or(u | (f << 1));
    }
    const int mode = (flags & 1) ? 1 : ((flags & 2) ? 2 : 0);

#pragma unroll
    for (int h = 0; h < 2; h++) {
        const int idx = tid + h * 256;
        const int gi = b * NN + idx;
        const float2 pxy = ((const float2*)pos)[gi];
        bool m;
        if (mode == 1)      m = ((const unsigned char*)mask)[gi] != 0;
        else if (mode == 2) m = ((const float*)mask)[gi] != 0.0f;
        else                m = ((const int*)mask)[gi] != 0;
        sp[idx] = make_float2(pxy.x + (m ? LARGEF : 0.0f), pxy.y);
        const int rloc = idx - bx * 8;
        if ((unsigned)rloc < 8u) spRow[rloc] = pxy;
    }
    __syncthreads();

    const int warp = tid >> 5, lane = tid & 31;
    const int i = bx * 8 + warp;
    const float2 pi = spRow[warp];
    const float xi = pi.x, yi = pi.y;
    const int  i_hi  = i >> 5;
    const bool pself = (lane == (i & 31));
    const float2* spl = sp + lane;

    unsigned cntUp = 0u, cntDn = 0u, cntLat = 0u;
    unsigned scntLo = 0u, scntHi = 0u;
    float mdUp2 = LARGEF, mdDn2 = LARGEF, mdLat2 = LARGEF;
    float smin2[8];
#pragma unroll
    for (int k = 0; k < 8; k++) smin2[k] = LARGEF;
    float sumd = 0.0f;

#pragma unroll
    for (int j0 = 0; j0 < 16; j0++) {
        const float2 p = spl[j0 << 5];
        const float dx = p.x - xi;
        const float dy = p.y - yi;
        const float d2 = __fadd_rn(__fadd_rn(__fmul_rn(dx, dx), __fmul_rn(dy, dy)), 1e-8f);
        float q2 = d2;
        if ((j0 == i_hi) && pself) q2 = LARGEF;
        const bool valid = q2 < 100000.0f;

        const float hay = 0.5f * fabsf(dy);
        const bool up = dx >  hay;
        const bool dn = dx < -hay;
        const bool lat = !up && !dn;

        const unsigned pat = (q2 < 9.0f)   ? 0x01010101u
                           : (q2 < 25.0f)  ? 0x01010100u
                           : (q2 < 64.0f)  ? 0x01010000u
                           : (q2 < 144.0f) ? 0x01000000u : 0u;
        if (up)  cntUp  += pat;
        if (dn)  cntDn  += pat;
        if (lat) cntLat += pat;

        if (up)  mdUp2  = fminf(mdUp2,  q2);
        if (dn)  mdDn2  = fminf(mdDn2,  q2);
        if (lat) mdLat2 = fminf(mdLat2, q2);

        const float su = dx + dy, sv = dy - dx;
        const int s = (dy < 0.0f)
            ? ((dx < 0.0f) ? ((sv > 0.0f) ? 0 : 1) : ((su < 0.0f) ? 2 : 3))
            : ((dx > 0.0f) ? ((sv < 0.0f) ? 4 : 5) : ((su > 0.0f) ? 6 : 7));

        const unsigned sinc = 1u << ((s & 3) << 3);
        if (valid) { if (s < 4) scntLo += sinc; else scntHi += sinc; }
#pragma unroll
        for (int k = 0; k < 8; k++)
            if (s == k) smin2[k] = fminf(smin2[k], q2);

        const float dist = d2 * rsqrtf(d2);
        if (valid) sumd += dist;
    }

    unsigned cntu[12];
#pragma unroll
    for (int t = 0; t < 4; t++) {
        cntu[0 * 4 + t] = uredsum((cntUp  >> (t * 8)) & 255u);
        cntu[1 * 4 + t] = uredsum((cntDn  >> (t * 8)) & 255u);
        cntu[2 * 4 + t] = uredsum((cntLat >> (t * 8)) & 255u);
    }
    unsigned scu[8];
#pragma unroll
    for (int k = 0; k < 8; k++)
        scu[k] = uredsum((k < 4 ? (scntLo >> (k * 8)) : (scntHi >> ((k - 4) * 8))) & 255u);
#pragma unroll
    for (int k = 0; k < 8; k++) smin2[k] = fredmin_pos(smin2[k]);
    mdUp2 = fredmin_pos(mdUp2); mdDn2 = fredmin_pos(mdDn2); mdLat2 = fredmin_pos(mdLat2);
    sumd = wsum(sumd);

    if (lane == 0) {
        float* o = g_feat + (size_t)(b * NN + i) * FEATN;
#pragma unroll
        for (int t = 0; t < 4; t++) {
            o[t * 3 + 0] = (float)cntu[0 * 4 + t];
            o[t * 3 + 1] = (float)cntu[1 * 4 + t];
            o[t * 3 + 2] = (float)cntu[2 * 4 + t];
        }
        o[12] = fminf(sqrtf(mdUp2)  / 10.0f, 1.0f);
        o[13] = fminf(sqrtf(mdDn2)  / 10.0f, 1.0f);
        o[14] = fminf(sqrtf(mdLat2) / 10.0f, 1.0f);
        unsigned cntv = 0;
#pragma unroll
        for (int k = 0; k < 8; k++) {
            o[15 + 2 * k] = (float)scu[k];
            o[16 + 2 * k] = fminf(sqrtf(smin2[k]) / 10.0f, 1.0f);
            cntv += scu[k];
        }
        o[31] = (float)(cntu[3] + cntu[7] + cntu[11]);
        float vc = fmaxf((float)cntv, 1.0f);
        o[32] = fminf(sumd / vc / 10.0f, 1.0f);
    }
}

// ---------------------------------------------------------------------------
// Encoder v9: 128 threads, 16 rows/block. Thread = 4 rows x 4 cols
// (cg = tid&31 -> cols 4cg..4cg+3, rg = tid>>5 -> rows 4rg..4rg+3).
// Each warp owns complete rows -> LN fully in-warp, no sred, syncwarp only.
// Per k4: 4 LDG.128 + 4 LDS.128 per 64 FFMA (was 12 mem / 64 FFMA).
// ---------------------------------------------------------------------------
#define XP 36
#define HP 132

__global__ __launch_bounds__(128, 8) void encoder_kernel(
    const float* __restrict__ W1, const float* __restrict__ b1,
    const float* __restrict__ gamma, const float* __restrict__ beta,
    const float* __restrict__ W2, const float* __restrict__ b2,
    float* __restrict__ out)
{
    __shared__ float sx[16 * XP];
    __shared__ float sh[16 * HP];

    const int tid = threadIdx.x;
    const int cg  = tid & 31;
    const int rg  = tid >> 5;          // 0..3 -> rows 4rg..4rg+3
    const int c0  = cg * 4;
    const int r0  = rg * 4;
    const int rowBase = blockIdx.x * 16;

    for (int idx = tid; idx < 16 * FEATN; idx += 128) {
        int r = idx / FEATN, f = idx - r * FEATN;
        sx[r * XP + f] = g_feat[(size_t)rowBase * FEATN + idx];
    }
    if (tid < 48) {
        int r = tid / 3;
        sx[r * XP + FEATN + tid % 3] = 0.0f;
    }
    __syncthreads();

    // ---- GEMM1: h = x @ W1 + b1 (4 rows x 4 cols per thread) ----
    float4 acc[4];
    {
        const float4 bb = __ldg((const float4*)&b1[c0]);
#pragma unroll
        for (int rr = 0; rr < 4; rr++) acc[rr] = bb;
#pragma unroll 2
        for (int f4 = 0; f4 < 32; f4 += 4) {
            const float4 w0 = __ldg((const float4*)&W1[(f4 + 0) * EE + c0]);
            const float4 w1 = __ldg((const float4*)&W1[(f4 + 1) * EE + c0]);
            const float4 w2 = __ldg((const float4*)&W1[(f4 + 2) * EE + c0]);
            const float4 w3 = __ldg((const float4*)&W1[(f4 + 3) * EE + c0]);
#pragma unroll
            for (int rr = 0; rr < 4; rr++) {
                const float4 xv = *(const float4*)&sx[(r0 + rr) * XP + f4];
                acc[rr].x += xv.x * w0.x + xv.y * w1.x + xv.z * w2.x + xv.w * w3.x;
                acc[rr].y += xv.x * w0.y + xv.y * w1.y + xv.z * w2.y + xv.w * w3.y;
                acc[rr].z += xv.x * w0.z + xv.y * w1.z + xv.z * w2.z + xv.w * w3.z;
                acc[rr].w += xv.x * w0.w + xv.y * w1.w + xv.z * w2.w + xv.w * w3.w;
            }
        }
        const float4 wl = __ldg((const float4*)&W1[32 * EE + c0]);
#pragma unroll
        for (int rr = 0; rr < 4; rr++) {
            const float xl = sx[(r0 + rr) * XP + 32];
            acc[rr].x += xl * wl.x;
            acc[rr].y += xl * wl.y;
            acc[rr].z += xl * wl.z;
            acc[rr].w += xl * wl.w;
        }
    }

    // ---- LN + GELU: warp owns all 128 cols of its 4 rows ----
    {
        const float4 gv  = __ldg((const float4*)&gamma[c0]);
        const float4 bev = __ldg((const float4*)&beta[c0]);
#pragma unroll
        for (int rr = 0; rr < 4; rr++) {
            const float4 a = acc[rr];
            const float s  = wsum(a.x + a.y + a.z + a.w);
            const float sq = wsum(a.x * a.x + a.y * a.y + a.z * a.z + a.w * a.w);
            const float mu  = s * (1.0f / 128.0f);
            const float var = sq * (1.0f / 128.0f) - mu * mu;
            const float inv = 1.0f / sqrtf(var + 1e-5f);
            float h0 = (a.x - mu) * inv * gv.x + bev.x;
            float h1 = (a.y - mu) * inv * gv.y + bev.y;
            float h2 = (a.z - mu) * inv * gv.z + bev.z;
            float h3 = (a.w - mu) * inv * gv.w + bev.w;
            h0 = 0.5f * h0 * (1.0f + erff(h0 * 0.70710678118654752440f));
            h1 = 0.5f * h1 * (1.0f + erff(h1 * 0.70710678118654752440f));
            h2 = 0.5f * h2 * (1.0f + erff(h2 * 0.70710678118654752440f));
            h3 = 0.5f * h3 * (1.0f + erff(h3 * 0.70710678118654752440f));
            *(float4*)&sh[(r0 + rr) * HP + c0] = make_float4(h0, h1, h2, h3);
        }
    }
    __syncwarp();   // GEMM2 reads only this warp's own rows

    // ---- GEMM2: out = h @ W2 + b2 (4 rows x 4 cols per thread) ----
    float4 oacc[4];
    {
        const float4 bo = __ldg((const float4*)&b2[c0]);
#pragma unroll
        for (int rr = 0; rr < 4; rr++) oacc[rr] = bo;
#pragma unroll 4
        for (int k4 = 0; k4 < EE; k4 += 4) {
            const float4 w0 = __ldg((const float4*)&W2[(k4 + 0) * EE + c0]);
            const float4 w1 = __ldg((const float4*)&W2[(k4 + 1) * EE + c0]);
            const float4 w2 = __ldg((const float4*)&W2[(k4 + 2) * EE + c0]);
            const float4 w3 = __ldg((const float4*)&W2[(k4 + 3) * EE + c0]);
#pragma unroll
            for (int rr = 0; rr < 4; rr++) {
                const float4 hv = *(const float4*)&sh[(r0 + rr) * HP + k4];
                oacc[rr].x += hv.x * w0.x + hv.y * w1.x + hv.z * w2.x + hv.w * w3.x;
                oacc[rr].y += hv.x * w0.y + hv.y * w1.y + hv.z * w2.y + hv.w * w3.y;
                oacc[rr].z += hv.x * w0.z + hv.y * w1.z + hv.z * w2.z + hv.w * w3.z;
                oacc[rr].w += hv.x * w0.w + hv.y * w1.w + hv.z * w2.w + hv.w * w3.w;
            }
        }
    }
#pragma unroll
    for (int rr = 0; rr < 4; rr++)
        *(float4*)&out[(size_t)(rowBase + r0 + rr) * EE + c0] = oacc[rr];
}

// ---------------------------------------------------------------------------
extern "C" void kernel_launch(void* const* d_in, const int* in_sizes, int n_in,
                              void* d_out, int out_size) {
    const float* positions = (const float*)d_in[0];
    const void*  mask      = d_in[1];
    const float* W1        = (const float*)d_in[2];
    const float* b1        = (const float*)d_in[3];
    const float* gamma     = (const float*)d_in[4];
    const float* beta      = (const float*)d_in[5];
    const float* W2        = (const float*)d_in[6];
    const float* b2        = (const float*)d_in[7];
    float* out = (float*)d_out;

    feat_kernel<<<dim3(NN / 8, BB), 256>>>(positions, mask);
    encoder_kernel<<<ROWS / 16, 128>>>(W1, b1, gamma, beta, W2, b2, out);
}

// round 17
// speedup vs baseline: 1.1463x; 1.0397x over previous
#include <cuda_runtime.h>
#include <math.h>

#define BB 64
#define NN 512
#define EE 128
#define FEATN 33
#define ROWS (BB*NN)
#define LARGEF 1000000.0f

__device__ float g_feat[(size_t)ROWS * FEATN];

// ---------------------------------------------------------------------------
// warp reduction helpers
// ---------------------------------------------------------------------------
__device__ __forceinline__ float wsum(float v) {
#pragma unroll
    for (int o = 16; o > 0; o >>= 1) v += __shfl_xor_sync(0xFFFFFFFFu, v, o);
    return v;
}
__device__ __forceinline__ unsigned uredsum(unsigned v) {
    return __reduce_add_sync(0xFFFFFFFFu, v);
}
__device__ __forceinline__ float fredmin_pos(float v) {
    return __int_as_float(__reduce_min_sync(0xFFFFFFFFu, __float_as_int(v)));
}

// ---------------------------------------------------------------------------
// Feature kernel (R14 form + ILP tweaks): 256 threads, 8 rows/block, 5 CTAs/SM.
// Pad penalty embedded in x; squared-distance domain; REDUX reductions.
// pat = 4 independent predicated adds; p prefetched one iteration ahead.
// ---------------------------------------------------------------------------
__global__ __launch_bounds__(256, 5) void feat_kernel(const float* __restrict__ pos,
                                                      const void* __restrict__ mask) {
    __shared__ float2 sp[NN];
    __shared__ float2 spRow[8];
    const int b   = blockIdx.y;
    const int bx  = blockIdx.x;
    const int tid = threadIdx.x;

    // ---- inline mask dtype detection (first 256 uint4 = 4KB) ----
    int flags;
    {
        const uint4 v = ((const uint4*)mask)[tid];
        int u = 0, f = 0;
        unsigned w;
        w = v.x; if (w == 0x3F800000u) f = 1; else if (w > 1u) u = 1;
        w = v.y; if (w == 0x3F800000u) f = 1; else if (w > 1u) u = 1;
        w = v.z; if (w == 0x3F800000u) f = 1; else if (w > 1u) u = 1;
        w = v.w; if (w == 0x3F800000u) f = 1; else if (w > 1u) u = 1;
        flags = __syncthreads_or(u | (f << 1));
    }
    const int mode = (flags & 1) ? 1 : ((flags & 2) ? 2 : 0);

#pragma unroll
    for (int h = 0; h < 2; h++) {
        const int idx = tid + h * 256;
        const int gi = b * NN + idx;
        const float2 pxy = ((const float2*)pos)[gi];
        bool m;
        if (mode == 1)      m = ((const unsigned char*)mask)[gi] != 0;
        else if (mode == 2) m = ((const float*)mask)[gi] != 0.0f;
        else                m = ((const int*)mask)[gi] != 0;
        sp[idx] = make_float2(pxy.x + (m ? LARGEF : 0.0f), pxy.y);
        const int rloc = idx - bx * 8;
        if ((unsigned)rloc < 8u) spRow[rloc] = pxy;
    }
    __syncthreads();

    const int warp = tid >> 5, lane = tid & 31;
    const int i = bx * 8 + warp;
    const float2 pi = spRow[warp];
    const float xi = pi.x, yi = pi.y;
    const int  i_hi  = i >> 5;
    const bool pself = (lane == (i & 31));
    const float2* spl = sp + lane;

    unsigned cntUp = 0u, cntDn = 0u, cntLat = 0u;
    unsigned scntLo = 0u, scntHi = 0u;
    float mdUp2 = LARGEF, mdDn2 = LARGEF, mdLat2 = LARGEF;
    float smin2[8];
#pragma unroll
    for (int k = 0; k < 8; k++) smin2[k] = LARGEF;
    float sumd = 0.0f;

    float2 pcur = spl[0];
#pragma unroll
    for (int j0 = 0; j0 < 16; j0++) {
        const float2 p = pcur;
        if (j0 < 15) pcur = spl[(j0 + 1) << 5];   // prefetch next iteration
        const float dx = p.x - xi;
        const float dy = p.y - yi;
        const float d2 = __fadd_rn(__fadd_rn(__fmul_rn(dx, dx), __fmul_rn(dy, dy)), 1e-8f);
        float q2 = d2;
        if ((j0 == i_hi) && pself) q2 = LARGEF;
        const bool valid = q2 < 100000.0f;

        const float hay = 0.5f * fabsf(dy);
        const bool up = dx >  hay;
        const bool dn = dx < -hay;
        const bool lat = !up && !dn;

        // cumulative thresholds (3,5,8,12)^2 -> byte fields, independent adds
        unsigned pat = 0u;
        if (q2 < 9.0f)   pat += 0x00000001u;
        if (q2 < 25.0f)  pat += 0x00000100u;
        if (q2 < 64.0f)  pat += 0x00010000u;
        if (q2 < 144.0f) pat += 0x01000000u;
        if (up)  cntUp  += pat;
        if (dn)  cntDn  += pat;
        if (lat) cntLat += pat;

        if (up)  mdUp2  = fminf(mdUp2,  q2);
        if (dn)  mdDn2  = fminf(mdDn2,  q2);
        if (lat) mdLat2 = fminf(mdLat2, q2);

        const float su = dx + dy, sv = dy - dx;
        const int s = (dy < 0.0f)
            ? ((dx < 0.0f) ? ((sv > 0.0f) ? 0 : 1) : ((su < 0.0f) ? 2 : 3))
            : ((dx > 0.0f) ? ((sv < 0.0f) ? 4 : 5) : ((su > 0.0f) ? 6 : 7));

        const unsigned sinc = 1u << ((s & 3) << 3);
        if (valid) { if (s < 4) scntLo += sinc; else scntHi += sinc; }
#pragma unroll
        for (int k = 0; k < 8; k++)
            if (s == k) smin2[k] = fminf(smin2[k], q2);

        const float dist = d2 * rsqrtf(d2);
        if (valid) sumd += dist;
    }

    unsigned cntu[12];
#pragma unroll
    for (int t = 0; t < 4; t++) {
        cntu[0 * 4 + t] = uredsum((cntUp  >> (t * 8)) & 255u);
        cntu[1 * 4 + t] = uredsum((cntDn  >> (t * 8)) & 255u);
        cntu[2 * 4 + t] = uredsum((cntLat >> (t * 8)) & 255u);
    }
    unsigned scu[8];
#pragma unroll
    for (int k = 0; k < 8; k++)
        scu[k] = uredsum((k < 4 ? (scntLo >> (k * 8)) : (scntHi >> ((k - 4) * 8))) & 255u);
#pragma unroll
    for (int k = 0; k < 8; k++) smin2[k] = fredmin_pos(smin2[k]);
    mdUp2 = fredmin_pos(mdUp2); mdDn2 = fredmin_pos(mdDn2); mdLat2 = fredmin_pos(mdLat2);
    sumd = wsum(sumd);

    if (lane == 0) {
        float* o = g_feat + (size_t)(b * NN + i) * FEATN;
#pragma unroll
        for (int t = 0; t < 4; t++) {
            o[t * 3 + 0] = (float)cntu[0 * 4 + t];
            o[t * 3 + 1] = (float)cntu[1 * 4 + t];
            o[t * 3 + 2] = (float)cntu[2 * 4 + t];
        }
        o[12] = fminf(sqrtf(mdUp2)  / 10.0f, 1.0f);
        o[13] = fminf(sqrtf(mdDn2)  / 10.0f, 1.0f);
        o[14] = fminf(sqrtf(mdLat2) / 10.0f, 1.0f);
        unsigned cntv = 0;
#pragma unroll
        for (int k = 0; k < 8; k++) {
            o[15 + 2 * k] = (float)scu[k];
            o[16 + 2 * k] = fminf(sqrtf(smin2[k]) / 10.0f, 1.0f);
            cntv += scu[k];
        }
        o[31] = (float)(cntu[3] + cntu[7] + cntu[11]);
        float vc = fmaxf((float)cntv, 1.0f);
        o[32] = fminf(sumd / vc / 10.0f, 1.0f);
    }
}

// ---------------------------------------------------------------------------
// Encoder (exact R14 form, measured 49.2us): 128 threads, 16 rows/block,
// 8 rows x 2 cols/thread, scalar FMA, W1/W2 via __ldg float2.
// ---------------------------------------------------------------------------
#define XP 36
#define HP 132

__global__ __launch_bounds__(128, 8) void encoder_kernel(
    const float* __restrict__ W1, const float* __restrict__ b1,
    const float* __restrict__ gamma, const float* __restrict__ beta,
    const float* __restrict__ W2, const float* __restrict__ b2,
    float* __restrict__ out)
{
    __shared__ float sx[16 * XP];
    __shared__ float sh[16 * HP];
    __shared__ float sred[16 * 4];

    const int tid   = threadIdx.x;
    const int cg    = tid & 63;
    const int rg    = tid >> 6;
    const int lane  = tid & 31;
    const int whalf = cg >> 5;
    const int c0    = cg * 2;
    const int r0    = rg * 8;
    const int rowBase = blockIdx.x * 16;

    for (int idx = tid; idx < 16 * FEATN; idx += 128) {
        int r = idx / FEATN, f = idx - r * FEATN;
        sx[r * XP + f] = g_feat[(size_t)rowBase * FEATN + idx];
    }
    if (tid < 48) {
        int r = tid / 3;
        sx[r * XP + FEATN + tid % 3] = 0.0f;
    }
    __syncthreads();

    float accA[8], accB[8];
    {
        const float2 bb = __ldg((const float2*)&b1[c0]);
#pragma unroll
        for (int rr = 0; rr < 8; rr++) { accA[rr] = bb.x; accB[rr] = bb.y; }
#pragma unroll 2
        for (int f4 = 0; f4 < 32; f4 += 4) {
            const float2 w0 = __ldg((const float2*)&W1[(f4 + 0) * EE + c0]);
            const float2 w1 = __ldg((const float2*)&W1[(f4 + 1) * EE + c0]);
            const float2 w2 = __ldg((const float2*)&W1[(f4 + 2) * EE + c0]);
            const float2 w3 = __ldg((const float2*)&W1[(f4 + 3) * EE + c0]);
#pragma unroll
            for (int rr = 0; rr < 8; rr++) {
                const float4 xv = *(const float4*)&sx[(r0 + rr) * XP + f4];
                accA[rr] += xv.x * w0.x + xv.y * w1.x + xv.z * w2.x + xv.w * w3.x;
                accB[rr] += xv.x * w0.y + xv.y * w1.y + xv.z * w2.y + xv.w * w3.y;
            }
        }
        const float2 wl = __ldg((const float2*)&W1[32 * EE + c0]);
#pragma unroll
        for (int rr = 0; rr < 8; rr++) {
            const float xl = sx[(r0 + rr) * XP + 32];
            accA[rr] += xl * wl.x;
            accB[rr] += xl * wl.y;
        }
    }

#pragma unroll
    for (int rr = 0; rr < 8; rr++) {
        float s  = wsum(accA[rr] + accB[rr]);
        float sq = wsum(accA[rr] * accA[rr] + accB[rr] * accB[rr]);
        if (lane == 0) {
            const int r = r0 + rr;
            sred[r * 4 + whalf * 2 + 0] = s;
            sred[r * 4 + whalf * 2 + 1] = sq;
        }
    }
    __syncthreads();

    const float2 gv  = __ldg((const float2*)&gamma[c0]);
    const float2 bev = __ldg((const float2*)&beta[c0]);
#pragma unroll
    for (int rr = 0; rr < 8; rr++) {
        const int r = r0 + rr;
        const float s  = sred[r * 4 + 0] + sred[r * 4 + 2];
        const float sq = sred[r * 4 + 1] + sred[r * 4 + 3];
        const float mu  = s * (1.0f / 128.0f);
        const float var = sq * (1.0f / 128.0f) - mu * mu;
        const float inv = 1.0f / sqrtf(var + 1e-5f);
        float hA = (accA[rr] - mu) * inv * gv.x + bev.x;
        float hB = (accB[rr] - mu) * inv * gv.y + bev.y;
        hA = 0.5f * hA * (1.0f + erff(hA * 0.70710678118654752440f));
        hB = 0.5f * hB * (1.0f + erff(hB * 0.70710678118654752440f));
        *(float2*)&sh[r * HP + c0] = make_float2(hA, hB);
    }
    __syncthreads();

    float oA[8], oB[8];
    {
        const float2 bo = __ldg((const float2*)&b2[c0]);
#pragma unroll
        for (int rr = 0; rr < 8; rr++) { oA[rr] = bo.x; oB[rr] = bo.y; }
#pragma unroll 4
        for (int k4 = 0; k4 < EE; k4 += 4) {
            const float2 w0 = __ldg((const float2*)&W2[(k4 + 0) * EE + c0]);
            const float2 w1 = __ldg((const float2*)&W2[(k4 + 1) * EE + c0]);
            const float2 w2 = __ldg((const float2*)&W2[(k4 + 2) * EE + c0]);
            const float2 w3 = __ldg((const float2*)&W2[(k4 + 3) * EE + c0]);
#pragma unroll
            for (int rr = 0; rr < 8; rr++) {
                const float4 hv = *(const float4*)&sh[(r0 + rr) * HP + k4];
                oA[rr] += hv.x * w0.x + hv.y * w1.x + hv.z * w2.x + hv.w * w3.x;
                oB[rr] += hv.x * w0.y + hv.y * w1.y + hv.z * w2.y + hv.w * w3.y;
            }
        }
    }
#pragma unroll
    for (int rr = 0; rr < 8; rr++) {
        float2 o2 = make_float2(oA[rr], oB[rr]);
        *(float2*)&out[(size_t)(rowBase + r0 + rr) * EE + c0] = o2;
    }
}

// ---------------------------------------------------------------------------
extern "C" void kernel_launch(void* const* d_in, const int* in_sizes, int n_in,
                              void* d_out, int out_size) {
    const float* positions = (const float*)d_in[0];
    const void*  mask      = d_in[1];
    const float* W1        = (const float*)d_in[2];
    const float* b1        = (const float*)d_in[3];
    const float* gamma     = (const float*)d_in[4];
    const float* beta      = (const float*)d_in[5];
    const float* W2        = (const float*)d_in[6];
    const float* b2        = (const float*)d_in[7];
    float* out = (float*)d_out;

    feat_kernel<<<dim3(NN / 8, BB), 256>>>(positions, mask);
    encoder_kernel<<<ROWS / 16, 128>>>(W1, b1, gamma, beta, W2, b2, out);
}